// round 3
// baseline (speedup 1.0000x reference)
#include <cuda_runtime.h>
#include <cuda_bf16.h>
#include <stdint.h>

#define SEQ 80
#define EMB 100
#define VOCAB 10000
#define BMAX 16384
#define WSTRIDE 72   // padded bf16 row stride: ldmatrix rows land on distinct 16B banks

// Precomputed emb @ Wx0 + b0 : [VOCAB, 64] fp32 (2.56 MB, L2-resident)
__device__ float g_embW0[VOCAB * 64];
// Transposed tokens [SEQ][B]
__device__ int g_tokT[SEQ * BMAX];

// ---------------------------------------------------------------------------
// Kernel 1: embW0[v][j] = sum_k emb[v][k] * Wx0[k][j] + b0[j]
// Register-tiled: each thread computes 4 outputs (1 vocab row x 4 units).
// ---------------------------------------------------------------------------
__global__ void __launch_bounds__(256) embw0_kernel(const float* __restrict__ emb,
                                                    const float* __restrict__ Wx0,
                                                    const float* __restrict__ b0) {
    __shared__ float sW[EMB * 64];   // [k][j]
    __shared__ float sE[16 * EMB];   // 16 vocab rows, contiguous
    int tid = threadIdx.x;
    for (int i = tid; i < EMB * 64; i += 256) sW[i] = Wx0[i];
    int vbase = blockIdx.x * 16;
    for (int i = tid; i < 16 * EMB; i += 256) sE[i] = emb[vbase * EMB + i];
    __syncthreads();

    int tcol = tid & 15;     // unit group: j = tcol*4 .. tcol*4+3
    int trow = tid >> 4;     // vocab row within block
    const float4* sW4 = reinterpret_cast<const float4*>(sW);
    float4 a = *reinterpret_cast<const float4*>(b0 + tcol * 4);
    const float* e = sE + trow * EMB;
    #pragma unroll 10
    for (int k = 0; k < EMB; ++k) {
        float ev = e[k];
        float4 w = sW4[k * 16 + tcol];
        a.x += ev * w.x; a.y += ev * w.y; a.z += ev * w.z; a.w += ev * w.w;
    }
    *reinterpret_cast<float4*>(g_embW0 + (vbase + trow) * 64 + tcol * 4) = a;
}

// ---------------------------------------------------------------------------
// Kernel 1b: token transpose [B][SEQ] -> [SEQ][B]
// ---------------------------------------------------------------------------
__global__ void __launch_bounds__(256) tok_transpose(const int* __restrict__ tokens, int B) {
    int b = blockIdx.x * 256 + threadIdx.x;
    if (b < B) {
        #pragma unroll
        for (int s = 0; s < SEQ; ++s)
            g_tokT[s * B + b] = tokens[b * SEQ + s];
    }
}

// ---------------------------------------------------------------------------
// PTX helpers
// ---------------------------------------------------------------------------
__device__ __forceinline__ void mma16816(float& d0, float& d1, float& d2, float& d3,
                                         uint32_t a0, uint32_t a1, uint32_t a2, uint32_t a3,
                                         uint32_t b0, uint32_t b1) {
    asm("mma.sync.aligned.m16n8k16.row.col.f32.bf16.bf16.f32 "
        "{%0,%1,%2,%3},{%4,%5,%6,%7},{%8,%9},{%0,%1,%2,%3};"
        : "+f"(d0), "+f"(d1), "+f"(d2), "+f"(d3)
        : "r"(a0), "r"(a1), "r"(a2), "r"(a3), "r"(b0), "r"(b1));
}

__device__ __forceinline__ void ldsm4(uint32_t& x, uint32_t& y, uint32_t& z, uint32_t& w,
                                      uint32_t saddr) {
    asm volatile("ldmatrix.sync.aligned.m8n8.x4.shared.b16 {%0,%1,%2,%3}, [%4];"
                 : "=r"(x), "=r"(y), "=r"(z), "=r"(w) : "r"(saddr));
}

__device__ __forceinline__ uint32_t packbf(float lo, float hi) {
    uint32_t r;
    asm("cvt.rn.bf16x2.f32 %0, %1, %2;" : "=r"(r) : "f"(hi), "f"(lo));
    return r;
}

__device__ __forceinline__ uint32_t tanh_bf16x2(uint32_t v) {
    uint32_t r;
    asm("tanh.approx.bf16x2 %0, %1;" : "=r"(r) : "r"(v));
    return r;
}

__device__ __forceinline__ float fast_tanh(float x) {
    float y;
    asm("tanh.approx.f32 %0, %1;" : "=f"(y) : "f"(x));
    return y;
}

__device__ __forceinline__ void bar_pair(int id) {
    asm volatile("bar.sync %0, 64;" :: "r"(id) : "memory");
}

// ---------------------------------------------------------------------------
// Kernel 2: layer-pipelined recurrence.
// CTA = 8 warps = 4 (producer, consumer) pairs; pair p = warps (p, p+4).
// Producer: layer 0 (gather + h0@Wh0 + tanh) -> h0 frags via smem double buffer.
// Consumer: layer 1 (h0@Wx1 + h1@Wh1 + tanh) + output head.
// One named bar.sync per pair per step.
// ---------------------------------------------------------------------------
__global__ void __launch_bounds__(256, 2) rnn_kernel(
    const float* __restrict__ Wh0,
    const float* __restrict__ Wx1,
    const float* __restrict__ Wh1,
    const float* __restrict__ b1,
    const float* __restrict__ Wout,
    const float* __restrict__ bout,
    float*       __restrict__ out,
    int B) {
    __shared__ __align__(16) uint16_t sWall[3 * 64 * WSTRIDE]; // Wh0^T, Wx1^T, Wh1^T (27.6KB)
    __shared__ __align__(16) uint2 sH0[4][2][8][32];           // h0 frag buffers (16KB)

    {
        const float* Ws[3] = {Wh0, Wx1, Wh1};
        #pragma unroll
        for (int w = 0; w < 3; ++w) {
            for (int i = threadIdx.x; i < 64 * 64; i += 256) {
                int k = i >> 6, n = i & 63;
                __nv_bfloat16 v = __float2bfloat16(Ws[w][i]);
                sWall[w * 64 * WSTRIDE + n * WSTRIDE + k] =
                    *reinterpret_cast<uint16_t*>(&v);
            }
        }
    }
    __syncthreads();

    const int lane = threadIdx.x & 31;
    const int wid  = threadIdx.x >> 5;
    const int g  = lane >> 2;   // row-in-tile
    const int tq = lane & 3;    // column pair
    const int laneoff = (lane & 7) * WSTRIDE + (lane >> 3) * 8;
    uint32_t swb = (uint32_t)__cvta_generic_to_shared(sWall);

    if (wid < 4) {
        // ================= PRODUCER: layer 0 =================
        const int pair = wid;
        const int base = (blockIdx.x * 4 + pair) * 16;
        int rc[2];
        #pragma unroll
        for (int i = 0; i < 2; ++i) {
            int r = base + g + 8 * i;
            rc[i] = r < B ? r : (B - 1);
        }
        const uint32_t aW0 = swb + 2 * laneoff;

        uint32_t h0f[16];
        #pragma unroll
        for (int i = 0; i < 16; ++i) h0f[i] = 0u;

        // preload gather for step 0 + token for step 1
        float gx[32];
        int tknext[2];
        #pragma unroll
        for (int i = 0; i < 2; ++i) {
            int tok = g_tokT[rc[i]];
            const float2* src = reinterpret_cast<const float2*>(g_embW0 + tok * 64) + tq;
            #pragma unroll
            for (int nt = 0; nt < 8; ++nt) {
                float2 v = src[nt * 4];
                gx[i * 16 + nt * 2]     = v.x;
                gx[i * 16 + nt * 2 + 1] = v.y;
            }
            tknext[i] = g_tokT[(SEQ > 1 ? 1 : 0) * B + rc[i]];
        }

        #pragma unroll 1
        for (int it = 0; it <= SEQ; ++it) {
            if (it < SEQ) {
                float accA[32];
                #pragma unroll
                for (int i = 0; i < 32; ++i) accA[i] = gx[i];

                // prefetch gather for step it+1 (uses tknext), then token for it+2
                #pragma unroll
                for (int i = 0; i < 2; ++i) {
                    const float2* src =
                        reinterpret_cast<const float2*>(g_embW0 + tknext[i] * 64) + tq;
                    #pragma unroll
                    for (int nt = 0; nt < 8; ++nt) {
                        float2 v = src[nt * 4];
                        gx[i * 16 + nt * 2]     = v.x;
                        gx[i * 16 + nt * 2 + 1] = v.y;
                    }
                }
                int ts2 = (it + 2 < SEQ) ? it + 2 : SEQ - 1;
                #pragma unroll
                for (int i = 0; i < 2; ++i) tknext[i] = g_tokT[ts2 * B + rc[i]];

                // accA += h0 @ Wh0
                #pragma unroll
                for (int kp = 0; kp < 2; ++kp) {
                    #pragma unroll
                    for (int nt = 0; nt < 8; ++nt) {
                        uint32_t off = 2 * (nt * 8 * WSTRIDE + kp * 32);
                        uint32_t x0, y0, z0, w0;
                        ldsm4(x0, y0, z0, w0, aW0 + off);
                        mma16816(accA[nt*2], accA[nt*2+1], accA[16+nt*2], accA[16+nt*2+1],
                                 h0f[(2*kp)*4+0], h0f[(2*kp)*4+1], h0f[(2*kp)*4+2], h0f[(2*kp)*4+3],
                                 x0, y0);
                        mma16816(accA[nt*2], accA[nt*2+1], accA[16+nt*2], accA[16+nt*2+1],
                                 h0f[(2*kp+1)*4+0], h0f[(2*kp+1)*4+1], h0f[(2*kp+1)*4+2], h0f[(2*kp+1)*4+3],
                                 z0, w0);
                    }
                }

                // h0 = tanh(accA)
                #pragma unroll
                for (int k = 0; k < 4; ++k) {
                    h0f[k*4+0] = tanh_bf16x2(packbf(accA[4*k],      accA[4*k+1]));
                    h0f[k*4+1] = tanh_bf16x2(packbf(accA[16+4*k],   accA[16+4*k+1]));
                    h0f[k*4+2] = tanh_bf16x2(packbf(accA[4*k+2],    accA[4*k+3]));
                    h0f[k*4+3] = tanh_bf16x2(packbf(accA[16+4*k+2], accA[16+4*k+3]));
                }

                // publish h0 frags
                int db = it & 1;
                #pragma unroll
                for (int rp = 0; rp < 8; ++rp)
                    sH0[pair][db][rp][lane] = make_uint2(h0f[2*rp], h0f[2*rp+1]);
            }
            bar_pair(pair);
        }
    } else {
        // ================= CONSUMER: layer 1 + head =================
        const int pair = wid - 4;
        const int base = (blockIdx.x * 4 + pair) * 16;
        int rraw[2];
        #pragma unroll
        for (int i = 0; i < 2; ++i) rraw[i] = base + g + 8 * i;

        const uint32_t aW1 = swb + 2 * (64 * WSTRIDE)  + 2 * laneoff;
        const uint32_t aW2 = swb + 2 * (128 * WSTRIDE) + 2 * laneoff;

        float b1f[16];
        #pragma unroll
        for (int nt = 0; nt < 8; ++nt) {
            b1f[nt * 2]     = b1[nt * 8 + tq * 2];
            b1f[nt * 2 + 1] = b1[nt * 8 + tq * 2 + 1];
        }

        uint32_t h1f[16];
        #pragma unroll
        for (int i = 0; i < 16; ++i) h1f[i] = 0u;
        float accB[32];

        #pragma unroll 1
        for (int it = 0; it <= SEQ; ++it) {
            if (it > 0) {
                // fetch h0 frags published by producer last iteration
                uint32_t h0L[16];
                int db = (it - 1) & 1;
                #pragma unroll
                for (int rp = 0; rp < 8; ++rp) {
                    uint2 v = sH0[pair][db][rp][lane];
                    h0L[2*rp]     = v.x;
                    h0L[2*rp + 1] = v.y;
                }

                // accB = b1
                #pragma unroll
                for (int nt = 0; nt < 8; ++nt) {
                    accB[nt * 2]          = b1f[nt * 2];
                    accB[nt * 2 + 1]      = b1f[nt * 2 + 1];
                    accB[16 + nt * 2]     = b1f[nt * 2];
                    accB[16 + nt * 2 + 1] = b1f[nt * 2 + 1];
                }

                // accB += h1 @ Wh1 (first: h1f in regs) ; accB += h0 @ Wx1
                #pragma unroll
                for (int kp = 0; kp < 2; ++kp) {
                    #pragma unroll
                    for (int nt = 0; nt < 8; ++nt) {
                        uint32_t off = 2 * (nt * 8 * WSTRIDE + kp * 32);
                        uint32_t x2, y2, z2, w2, x1, y1, z1, w1;
                        ldsm4(x2, y2, z2, w2, aW2 + off);
                        ldsm4(x1, y1, z1, w1, aW1 + off);
                        mma16816(accB[nt*2], accB[nt*2+1], accB[16+nt*2], accB[16+nt*2+1],
                                 h1f[(2*kp)*4+0], h1f[(2*kp)*4+1], h1f[(2*kp)*4+2], h1f[(2*kp)*4+3],
                                 x2, y2);
                        mma16816(accB[nt*2], accB[nt*2+1], accB[16+nt*2], accB[16+nt*2+1],
                                 h1f[(2*kp+1)*4+0], h1f[(2*kp+1)*4+1], h1f[(2*kp+1)*4+2], h1f[(2*kp+1)*4+3],
                                 z2, w2);
                        mma16816(accB[nt*2], accB[nt*2+1], accB[16+nt*2], accB[16+nt*2+1],
                                 h0L[(2*kp)*4+0], h0L[(2*kp)*4+1], h0L[(2*kp)*4+2], h0L[(2*kp)*4+3],
                                 x1, y1);
                        mma16816(accB[nt*2], accB[nt*2+1], accB[16+nt*2], accB[16+nt*2+1],
                                 h0L[(2*kp+1)*4+0], h0L[(2*kp+1)*4+1], h0L[(2*kp+1)*4+2], h0L[(2*kp+1)*4+3],
                                 z1, w1);
                    }
                }

                // h1 = tanh(accB)
                #pragma unroll
                for (int k = 0; k < 4; ++k) {
                    h1f[k*4+0] = tanh_bf16x2(packbf(accB[4*k],      accB[4*k+1]));
                    h1f[k*4+1] = tanh_bf16x2(packbf(accB[16+4*k],   accB[16+4*k+1]));
                    h1f[k*4+2] = tanh_bf16x2(packbf(accB[4*k+2],    accB[4*k+3]));
                    h1f[k*4+3] = tanh_bf16x2(packbf(accB[16+4*k+2], accB[16+4*k+3]));
                }
            }
            bar_pair(pair);
        }

        // ---- head: sigmoid(tanh(accB) @ Wout + bout) ----
        float wo[16];
        #pragma unroll
        for (int nt = 0; nt < 8; ++nt) {
            float2 v = *reinterpret_cast<const float2*>(Wout + nt * 8 + tq * 2);
            wo[nt * 2] = v.x; wo[nt * 2 + 1] = v.y;
        }
        float bo = bout[0];
        #pragma unroll
        for (int i = 0; i < 2; ++i) {
            float s = 0.f;
            #pragma unroll
            for (int nt = 0; nt < 8; ++nt) {
                s += fast_tanh(accB[i * 16 + nt * 2])     * wo[nt * 2];
                s += fast_tanh(accB[i * 16 + nt * 2 + 1]) * wo[nt * 2 + 1];
            }
            s += __shfl_xor_sync(0xffffffffu, s, 1);
            s += __shfl_xor_sync(0xffffffffu, s, 2);
            if (tq == 0 && rraw[i] < B)
                out[rraw[i]] = 1.0f / (1.0f + __expf(-(s + bo)));
        }
    }
}

// ---------------------------------------------------------------------------
extern "C" void kernel_launch(void* const* d_in, const int* in_sizes, int n_in,
                              void* d_out, int out_size) {
    const int*   tokens = (const int*)  d_in[0];
    const float* emb    = (const float*)d_in[1];
    const float* Wx0    = (const float*)d_in[2];
    const float* Wh0    = (const float*)d_in[3];
    const float* b0     = (const float*)d_in[4];
    const float* Wx1    = (const float*)d_in[5];
    const float* Wh1    = (const float*)d_in[6];
    const float* b1     = (const float*)d_in[7];
    const float* Wout   = (const float*)d_in[8];
    const float* bout   = (const float*)d_in[9];
    float* out = (float*)d_out;

    int B = in_sizes[0] / SEQ;
    if (B > BMAX) B = BMAX;

    embw0_kernel<<<VOCAB / 16, 256>>>(emb, Wx0, b0);
    tok_transpose<<<(B + 255) / 256, 256>>>(tokens, B);

    int nblocks = (B + 63) / 64;
    rnn_kernel<<<nblocks, 256>>>(Wh0, Wx1, Wh1, b1, Wout, bout, out, B);
}